// round 12
// baseline (speedup 1.0000x reference)
#include <cuda_runtime.h>
#include <cuda_bf16.h>
#include <cuda_fp16.h>
#include <stdint.h>

// GCN graph classifier: 2x (GCNConv + ReLU) -> global_mean_pool -> Linear
// N=100k, E=1.6M, H=128, G=512, OUT=2.
//
// R12 vs R11 (258.4us):
//  - scan_dis+scan2+scan3 fused into ONE decoupled-lookback scan kernel
//    (flags in g_bsum sign bit, cleared by prep1; all blocks co-resident)
//  - 2-chunk agg1 || GEMM2 pipeline (GEMM2 tile reads g_hh only in-tile;
//    separate g_xwh2 output keeps it WAR-free). 2 chunks, not 4: wave tails.
//  - everything else as R11: split-bf16 TC GEMMs, fp16 intermediates,
//    full-grid aggs, standalone poolfinal, CSR || GEMM1 fork.

#define HD   128
#define NMAX 100352
#define EMAX 1605632
#define WPAD 136          // padded k-stride (bf16 elems) for smem tiles

__device__ __align__(16) float g_deg[NMAX];          // zero-init; reset by scan
__device__ __align__(16) float g_dis[NMAX];
__device__ __align__(16) int   g_row[EMAX];
__device__ __align__(16) int   g_col[EMAX];
__device__ __align__(16) int   g_batch[NMAX];
__device__ __align__(16) int   g_cnt[NMAX];          // zero-init; reset by scan
__device__ __align__(16) int   g_off[NMAX + 1];
__device__ __align__(16) int   g_cur[NMAX];
__device__ __align__(16) int   g_bsum[128];          // lookback aggregates+flag
__device__ __align__(16) int2  g_edge[EMAX];         // {src row, coef bits}
__device__ __align__(16) __half g_xwh[(size_t)NMAX * HD];  // GEMM1 out (fp16)
__device__ __align__(16) __half g_xwh2[(size_t)NMAX * HD]; // GEMM2 out (fp16)
__device__ __align__(16) __half g_hh[(size_t)NMAX * HD];   // agg out (fp16)
__device__ __align__(16) __nv_bfloat16 g_Wh[2][HD * HD];   // W^T hi, [n][k]
__device__ __align__(16) __nv_bfloat16 g_Wl[2][HD * HD];   // W^T lo

// ---------------------------------------------------------------------------
// dtype detection (int64 arrays have zero hi-words at odd 32-bit indices)
// ---------------------------------------------------------------------------
__device__ __forceinline__ int detect_ei64(const int* ei32)
{
    int lane = threadIdx.x & 31;
    int v = ei32[2 * lane + 1];
    return __all_sync(0xffffffffu, v == 0);
}

__device__ __forceinline__ int detect_b64(const int* b32, int n)
{
    int lane = threadIdx.x & 31;
    int base = (n > 64) ? ((n - 64) & ~1) : 0;
    int v = b32[base + 2 * lane + 1];
    return __all_sync(0xffffffffu, v == 0);
}

// ---------------------------------------------------------------------------
// prep1: convert edge_index + batch, fused histogram/degree atomics;
// block 0 also clears the lookback flags for the scan kernel.
// ---------------------------------------------------------------------------
__global__ void k_prep1(const void* __restrict__ ei, const void* __restrict__ bt,
                        const float* __restrict__ ew, int n, int e)
{
    __shared__ int s_ei64, s_b64;
    const int* ei32 = (const int*)ei;
    const int* bt32 = (const int*)bt;
    int tid = threadIdx.x;
    if (tid < 32) {
        int r = detect_ei64(ei32);
        if (tid == 0) s_ei64 = r;
    } else if (tid < 64) {
        int r = detect_b64(bt32, n);
        if (tid == 32) s_b64 = r;
    }
    if (blockIdx.x == 0 && tid < 128)
        g_bsum[tid] = 0;                 // clear lookback flags
    __syncthreads();

    int i = blockIdx.x * blockDim.x + tid;
    if (i < e) {
        int r, c;
        if (s_ei64) {
            const long long* p = (const long long*)ei;
            r = (int)p[i];
            c = (int)p[(size_t)e + i];
        } else {
            r = ei32[i];
            c = ei32[e + i];
        }
        g_row[i] = r;
        g_col[i] = c;
        atomicAdd(&g_deg[c], ew[i]);
        atomicAdd(&g_cnt[c], 1);
    }
    if (i < n)
        g_batch[i] = s_b64 ? (int)((const long long*)bt)[i] : bt32[i];
}

// ---------------------------------------------------------------------------
// fused single-pass scan (decoupled lookback) + dis:
//  blocks [0,nb):    scan g_cnt -> exclusive g_off/g_cur, reset g_cnt
//  blocks [nb,...):  g_dis = rsqrt(g_deg+1), reset g_deg
// All blocks co-resident (196 blocks, 2/SM), so polling cannot deadlock.
// ---------------------------------------------------------------------------
__global__ void k_scan_all(int n, int nb, int e)
{
    int b = blockIdx.x;
    if (b < nb) {
        __shared__ int s[1024];
        __shared__ int sbase;
        int tid = threadIdx.x;
        int i = b * 1024 + tid;
        int v0 = (i < n) ? g_cnt[i] : 0;
        s[tid] = v0;
        __syncthreads();
        for (int off = 1; off < 1024; off <<= 1) {
            int t = 0;
            if (tid >= off) t = s[tid - off];
            __syncthreads();
            if (tid >= off) s[tid] += t;
            __syncthreads();
        }
        // publish this block's aggregate with flag (sign bit) ASAP
        if (tid == 0) {
            sbase = 0;
            atomicExch(&g_bsum[b], (int)(0x80000000u | (unsigned)s[1023]));
        }
        __syncthreads();
        // non-chained lookback: thread tid polls predecessor tid's aggregate
        if (tid < b) {
            unsigned v;
            do {
                v = (unsigned)atomicAdd(&g_bsum[tid], 0);
            } while (!(v & 0x80000000u));
            atomicAdd(&sbase, (int)(v & 0x7fffffffu));
        }
        __syncthreads();
        if (i < n) {
            int ex = sbase + s[tid] - v0;   // exclusive prefix
            g_off[i] = ex;
            g_cur[i] = ex;
            g_cnt[i] = 0;                    // reset for next invocation
        }
        if (b == 0 && tid == 0) g_off[n] = e;
    } else {
        int i = (b - nb) * 1024 + threadIdx.x;
        if (i < n) {
            g_dis[i] = rsqrtf(g_deg[i] + 1.0f);  // +1 = self-loop
            g_deg[i] = 0.0f;                      // reset for next invocation
        }
    }
}

__global__ void k_scatter(const float* __restrict__ ew, int e)
{
    int i = blockIdx.x * blockDim.x + threadIdx.x;
    if (i >= e) return;
    int r = g_row[i];
    int c = g_col[i];
    float coef = g_dis[r] * ew[i] * g_dis[c];
    int slot = atomicAdd(&g_cur[c], 1);
    g_edge[slot] = make_int2(r, __float_as_int(coef));
}

// ---------------------------------------------------------------------------
// W split: W[k][n] fp32 -> transposed bf16 hi/lo [n][k]
// ---------------------------------------------------------------------------
__global__ void k_wsplit(const float* __restrict__ W1, const float* __restrict__ W2)
{
    int idx = blockIdx.x * blockDim.x + threadIdx.x;
    if (idx >= HD * HD) return;
    int k = idx >> 7, nn = idx & 127;
    float w1 = W1[idx], w2 = W2[idx];
    __nv_bfloat16 h1 = __float2bfloat16(w1);
    __nv_bfloat16 h2 = __float2bfloat16(w2);
    int o = nn * HD + k;
    g_Wh[0][o] = h1;
    g_Wl[0][o] = __float2bfloat16(w1 - __bfloat162float(h1));
    g_Wh[1][o] = h2;
    g_Wl[1][o] = __float2bfloat16(w2 - __bfloat162float(h2));
}

// ---------------------------------------------------------------------------
// tensor-core GEMM: Cout[rows x 128] = A[rows x 128] @ W  (split-bf16)
// A = Xin (fp32) when useH=0, g_hh (fp16) when useH=1. rowStart offsets tiles.
// Cout: g_xwh (useH=0) or g_xwh2 (useH=1).
// ---------------------------------------------------------------------------
#define MMA16816(d, a, b)                                                     \
    asm volatile("mma.sync.aligned.m16n8k16.row.col.f32.bf16.bf16.f32 "       \
                 "{%0,%1,%2,%3}, {%4,%5,%6,%7}, {%8,%9}, {%0,%1,%2,%3};"      \
                 : "+f"((d)[0]), "+f"((d)[1]), "+f"((d)[2]), "+f"((d)[3])     \
                 : "r"((a)[0]), "r"((a)[1]), "r"((a)[2]), "r"((a)[3]),        \
                   "r"((b)[0]), "r"((b)[1]))

__global__ void __launch_bounds__(256) k_gemm_tc(const float* __restrict__ Xin,
                                                 int widx, int useH,
                                                 int rowStart, int n)
{
    extern __shared__ __align__(16) char smraw[];
    __nv_bfloat16* Ah = (__nv_bfloat16*)smraw;       // [128][WPAD]
    __nv_bfloat16* Al = Ah + 128 * WPAD;
    __nv_bfloat16* Bh = Al + 128 * WPAD;             // W^T [n][k], [128][WPAD]
    __nv_bfloat16* Bl = Bh + 128 * WPAD;

    __half* Cout = useH ? g_xwh2 : g_xwh;
    int tid = threadIdx.x;
    int rowBase = rowStart + blockIdx.x * 128;

    // stage + split A tile
#pragma unroll
    for (int i = 0; i < 16; i++) {
        int f4 = tid + i * 256;
        int r = f4 >> 5;
        int c4 = (f4 & 31) * 4;
        int ar = min(rowBase + r, n - 1);
        float4 v;
        if (useH) {
            uint2 hv = *(const uint2*)(g_hh + (size_t)ar * HD + c4);
            float2 f01 = __half22float2(*(__half2*)&hv.x);
            float2 f23 = __half22float2(*(__half2*)&hv.y);
            v = make_float4(f01.x, f01.y, f23.x, f23.y);
        } else {
            v = *(const float4*)(Xin + (size_t)ar * HD + c4);
        }
        __nv_bfloat16 hx = __float2bfloat16(v.x);
        __nv_bfloat16 hy = __float2bfloat16(v.y);
        __nv_bfloat16 hz = __float2bfloat16(v.z);
        __nv_bfloat16 hw = __float2bfloat16(v.w);
        __nv_bfloat16 lx = __float2bfloat16(v.x - __bfloat162float(hx));
        __nv_bfloat16 ly = __float2bfloat16(v.y - __bfloat162float(hy));
        __nv_bfloat16 lz = __float2bfloat16(v.z - __bfloat162float(hz));
        __nv_bfloat16 lw = __float2bfloat16(v.w - __bfloat162float(hw));
        __nv_bfloat162 h01, h23, l01, l23;
        h01.x = hx; h01.y = hy; h23.x = hz; h23.y = hw;
        l01.x = lx; l01.y = ly; l23.x = lz; l23.y = lw;
        uint2 uh, ul;
        uh.x = *(uint32_t*)&h01; uh.y = *(uint32_t*)&h23;
        ul.x = *(uint32_t*)&l01; ul.y = *(uint32_t*)&l23;
        *(uint2*)&Ah[r * WPAD + c4] = uh;
        *(uint2*)&Al[r * WPAD + c4] = ul;
    }

    // stage W^T tiles
#pragma unroll
    for (int i = 0; i < 8; i++) {
        int idx8 = (tid + i * 256) * 8;
        int r = idx8 >> 7;
        int c = idx8 & 127;
        *(uint4*)&Bh[r * WPAD + c] = *(const uint4*)&g_Wh[widx][idx8];
        *(uint4*)&Bl[r * WPAD + c] = *(const uint4*)&g_Wl[widx][idx8];
    }
    __syncthreads();

    int lane = tid & 31;
    int w = tid >> 5;
    int g = lane >> 2;
    int t = lane & 3;
    int wm0 = (w & 1) * 64;
    int wn0 = (w >> 1) * 32;

    float acc[4][4][4];
#pragma unroll
    for (int mb = 0; mb < 4; mb++)
#pragma unroll
        for (int nb = 0; nb < 4; nb++)
#pragma unroll
            for (int q = 0; q < 4; q++) acc[mb][nb][q] = 0.0f;

#pragma unroll
    for (int ks = 0; ks < 8; ks++) {
        int k0 = ks * 16 + t * 2;
        uint32_t ah[4][4], al[4][4];
#pragma unroll
        for (int mb = 0; mb < 4; mb++) {
            int r0 = wm0 + mb * 16 + g;
            ah[mb][0] = *(const uint32_t*)&Ah[r0 * WPAD + k0];
            ah[mb][1] = *(const uint32_t*)&Ah[(r0 + 8) * WPAD + k0];
            ah[mb][2] = *(const uint32_t*)&Ah[r0 * WPAD + k0 + 8];
            ah[mb][3] = *(const uint32_t*)&Ah[(r0 + 8) * WPAD + k0 + 8];
            al[mb][0] = *(const uint32_t*)&Al[r0 * WPAD + k0];
            al[mb][1] = *(const uint32_t*)&Al[(r0 + 8) * WPAD + k0];
            al[mb][2] = *(const uint32_t*)&Al[r0 * WPAD + k0 + 8];
            al[mb][3] = *(const uint32_t*)&Al[(r0 + 8) * WPAD + k0 + 8];
        }
        uint32_t bh[4][2], bl[4][2];
#pragma unroll
        for (int nb = 0; nb < 4; nb++) {
            int nr = wn0 + nb * 8 + g;
            bh[nb][0] = *(const uint32_t*)&Bh[nr * WPAD + k0];
            bh[nb][1] = *(const uint32_t*)&Bh[nr * WPAD + k0 + 8];
            bl[nb][0] = *(const uint32_t*)&Bl[nr * WPAD + k0];
            bl[nb][1] = *(const uint32_t*)&Bl[nr * WPAD + k0 + 8];
        }
#pragma unroll
        for (int mb = 0; mb < 4; mb++)
#pragma unroll
            for (int nb = 0; nb < 4; nb++) {
                MMA16816(acc[mb][nb], ah[mb], bh[nb]);
                MMA16816(acc[mb][nb], ah[mb], bl[nb]);
                MMA16816(acc[mb][nb], al[mb], bh[nb]);
            }
    }

    // write C as fp16
#pragma unroll
    for (int mb = 0; mb < 4; mb++) {
#pragma unroll
        for (int nb = 0; nb < 4; nb++) {
            int r0 = rowBase + wm0 + mb * 16 + g;
            int c0 = wn0 + nb * 8 + t * 2;
            if (r0 < n) {
                __half2 v0 = __floats2half2_rn(acc[mb][nb][0], acc[mb][nb][1]);
                *(__half2*)&Cout[(size_t)r0 * HD + c0] = v0;
            }
            if (r0 + 8 < n) {
                __half2 v1 = __floats2half2_rn(acc[mb][nb][2], acc[mb][nb][3]);
                *(__half2*)&Cout[(size_t)(r0 + 8) * HD + c0] = v1;
            }
        }
    }
}

// ---------------------------------------------------------------------------
// aggregation: fp16 gathers, fp32 accumulate, fp16 output to g_hh.
// warp per node, node range [base,end). srcSel: 0 -> g_xwh, 1 -> g_xwh2.
// ---------------------------------------------------------------------------
__device__ __forceinline__ void h4_acc(float4& acc, uint2 u, float c)
{
    float2 f01 = __half22float2(*(__half2*)&u.x);
    float2 f23 = __half22float2(*(__half2*)&u.y);
    acc.x += c * f01.x;
    acc.y += c * f01.y;
    acc.z += c * f23.x;
    acc.w += c * f23.y;
}

__global__ void k_agg(const float* __restrict__ bias, int srcSel,
                      int base, int end)
{
    int gw = base + ((blockIdx.x * blockDim.x + threadIdx.x) >> 5);
    int lane = threadIdx.x & 31;
    if (gw >= end) return;

    const uint2* x2 = (const uint2*)(srcSel ? g_xwh2 : g_xwh);
    float sc = g_dis[gw];
    float4 acc = make_float4(0.f, 0.f, 0.f, 0.f);
    h4_acc(acc, x2[(size_t)gw * 32 + lane], sc * sc);

    int p  = g_off[gw];
    int p1 = g_off[gw + 1];
    for (; p + 3 < p1; p += 4) {
        int2 e0 = g_edge[p];
        int2 e1 = g_edge[p + 1];
        int2 e2 = g_edge[p + 2];
        int2 e3 = g_edge[p + 3];
        uint2 u0 = x2[(size_t)e0.x * 32 + lane];
        uint2 u1 = x2[(size_t)e1.x * 32 + lane];
        uint2 u2 = x2[(size_t)e2.x * 32 + lane];
        uint2 u3 = x2[(size_t)e3.x * 32 + lane];
        h4_acc(acc, u0, __int_as_float(e0.y));
        h4_acc(acc, u1, __int_as_float(e1.y));
        h4_acc(acc, u2, __int_as_float(e2.y));
        h4_acc(acc, u3, __int_as_float(e3.y));
    }
    for (; p < p1; p++) {
        int2 e0 = g_edge[p];
        uint2 u0 = x2[(size_t)e0.x * 32 + lane];
        h4_acc(acc, u0, __int_as_float(e0.y));
    }

    float4 bb = ((const float4*)bias)[lane];
    __half2 h01 = __floats2half2_rn(fmaxf(acc.x + bb.x, 0.0f),
                                    fmaxf(acc.y + bb.y, 0.0f));
    __half2 h23 = __floats2half2_rn(fmaxf(acc.z + bb.z, 0.0f),
                                    fmaxf(acc.w + bb.w, 0.0f));
    uint2 u;
    u.x = *(uint32_t*)&h01;
    u.y = *(uint32_t*)&h23;
    *(uint2*)&g_hh[(size_t)gw * HD + 4 * lane] = u;
}

// ---------------------------------------------------------------------------
// pooling + classifier over fp16 g_hh (binary-search graph bounds)
// ---------------------------------------------------------------------------
__global__ void k_poolfinal(const float* __restrict__ Wl, const float* __restrict__ bl,
                            float* __restrict__ out, int n)
{
    int g = blockIdx.x;
    int f = threadIdx.x;
    __shared__ int sb[2];
    __shared__ float r0[128], r1[128];

    if (f < 2) {
        int target = g + f;
        int lo = 0, hi = n;
        while (lo < hi) {
            int mid = (lo + hi) >> 1;
            if (g_batch[mid] < target) lo = mid + 1; else hi = mid;
        }
        sb[f] = lo;
    }
    __syncthreads();
    int s = sb[0], t = sb[1];

    float acc = 0.0f;
    for (int i = s; i < t; i++)
        acc += __half2float(g_hh[(size_t)i * HD + f]);
    float pooled = acc / fmaxf((float)(t - s), 1.0f);

    r0[f] = pooled * Wl[f * 2 + 0];
    r1[f] = pooled * Wl[f * 2 + 1];
    __syncthreads();
#pragma unroll
    for (int off = 64; off > 0; off >>= 1) {
        if (f < off) { r0[f] += r0[f + off]; r1[f] += r1[f + off]; }
        __syncthreads();
    }
    if (f == 0) {
        out[g * 2 + 0] = r0[0] + bl[0];
        out[g * 2 + 1] = r1[0] + bl[1];
    }
}

// ---------------------------------------------------------------------------
static inline int ceil_div_i(int a, int b) { return (a + b - 1) / b; }

extern "C" void kernel_launch(void* const* d_in, const int* in_sizes, int n_in,
                              void* d_out, int out_size)
{
    (void)n_in;
    const float* x  = (const float*)d_in[0];
    const void*  ei = d_in[1];
    const float* ew = (const float*)d_in[2];
    const void*  bt = d_in[3];
    const float* W1 = (const float*)d_in[4];
    const float* b1 = (const float*)d_in[5];
    const float* W2 = (const float*)d_in[6];
    const float* b2 = (const float*)d_in[7];
    const float* Wl = (const float*)d_in[8];
    const float* bl = (const float*)d_in[9];
    float* out = (float*)d_out;

    int n = in_sizes[0] / HD;
    int e = in_sizes[2];
    int G = out_size / 2;

    int eb = ceil_div_i(e, 256);
    int nb = ceil_div_i(n, 1024);
    int gemm_blocks = ceil_div_i(n, 128);

    int gemm_smem = 4 * 128 * WPAD * (int)sizeof(__nv_bfloat16);  // 139264
    cudaFuncSetAttribute(k_gemm_tc, cudaFuncAttributeMaxDynamicSharedMemorySize,
                         gemm_smem);

    // fork side stream + events
    cudaStream_t s2 = 0;
    cudaEvent_t evA = 0, evB = 0, evC0 = 0, evC1 = 0, evG0 = 0, evG1 = 0;
    bool forked = false;
    do {
        if (cudaStreamCreateWithFlags(&s2, cudaStreamNonBlocking) != cudaSuccess) break;
        if (cudaEventCreateWithFlags(&evA, cudaEventDisableTiming) != cudaSuccess) break;
        if (cudaEventCreateWithFlags(&evB, cudaEventDisableTiming) != cudaSuccess) break;
        if (cudaEventCreateWithFlags(&evC0, cudaEventDisableTiming) != cudaSuccess) break;
        if (cudaEventCreateWithFlags(&evC1, cudaEventDisableTiming) != cudaSuccess) break;
        if (cudaEventCreateWithFlags(&evG0, cudaEventDisableTiming) != cudaSuccess) break;
        if (cudaEventCreateWithFlags(&evG1, cudaEventDisableTiming) != cudaSuccess) break;
        if (cudaEventRecord(evA, 0) != cudaSuccess) break;
        if (cudaStreamWaitEvent(s2, evA, 0) != cudaSuccess) break;
        forked = true;
    } while (0);

    if (forked) {
        // side: wsplit + GEMM1 (writes g_xwh) overlap the CSR build
        k_wsplit<<<ceil_div_i(HD * HD, 256), 256, 0, s2>>>(W1, W2);
        k_gemm_tc<<<gemm_blocks, 256, gemm_smem, s2>>>(x, 0, 0, 0, n);
        cudaEventRecord(evB, s2);

        // main: CSR build (prep1 clears lookback flags; deg/cnt pre-zeroed)
        k_prep1<<<eb, 256>>>(ei, bt, ew, n, e);
        k_scan_all<<<2 * nb, 1024>>>(n, nb, e);
        k_scatter<<<eb, 256>>>(ew, e);
        cudaStreamWaitEvent(0, evB, 0);

        // 2-chunk pipeline: agg1 (main) || GEMM2 (side, own buffer g_xwh2)
        int halfTiles = gemm_blocks / 2;
        int mid = halfTiles * 128;                    // tile-aligned boundary
        k_agg<<<ceil_div_i(mid, 8), 256>>>(b1, 0, 0, mid);
        cudaEventRecord(evC0, 0);
        k_agg<<<ceil_div_i(n - mid, 8), 256>>>(b1, 0, mid, n);
        cudaEventRecord(evC1, 0);

        cudaStreamWaitEvent(s2, evC0, 0);
        k_gemm_tc<<<halfTiles, 256, gemm_smem, s2>>>(x, 1, 1, 0, n);
        cudaEventRecord(evG0, s2);
        cudaStreamWaitEvent(s2, evC1, 0);
        k_gemm_tc<<<gemm_blocks - halfTiles, 256, gemm_smem, s2>>>(x, 1, 1, mid, n);
        cudaEventRecord(evG1, s2);

        cudaStreamWaitEvent(0, evG0, 0);
        cudaStreamWaitEvent(0, evG1, 0);

        // layer-2 aggregate (full grid) + pooling/classifier
        k_agg<<<ceil_div_i(n, 8), 256>>>(b2, 1, 0, n);
        k_poolfinal<<<G, 128>>>(Wl, bl, out, n);
    } else {
        // sequential fallback
        k_wsplit<<<ceil_div_i(HD * HD, 256), 256>>>(W1, W2);
        k_gemm_tc<<<gemm_blocks, 256, gemm_smem>>>(x, 0, 0, 0, n);
        k_prep1<<<eb, 256>>>(ei, bt, ew, n, e);
        k_scan_all<<<2 * nb, 1024>>>(n, nb, e);
        k_scatter<<<eb, 256>>>(ew, e);
        k_agg<<<ceil_div_i(n, 8), 256>>>(b1, 0, 0, n);
        k_gemm_tc<<<gemm_blocks, 256, gemm_smem>>>(x, 1, 1, 0, n);
        k_agg<<<ceil_div_i(n, 8), 256>>>(b2, 1, 0, n);
        k_poolfinal<<<G, 128>>>(Wl, bl, out, n);
    }
}

// round 13
// speedup vs baseline: 1.0855x; 1.0855x over previous
#include <cuda_runtime.h>
#include <cuda_bf16.h>
#include <cuda_fp16.h>
#include <stdint.h>

// GCN graph classifier: 2x (GCNConv + ReLU) -> global_mean_pool -> Linear
// N=100k, E=1.6M, H=128, G=512, OUT=2.
//
// R13 vs R11 (258.4us best; R12's chunk pipeline regressed and is retired):
//  - sequential agg1 -> GEMM2 -> agg2 (R11 topology, full grids)
//  - ONE packed 64-bit atomic per edge in prep1: hi32 = count, lo32 =
//    fixed-point (2^24) edge-weight sum. Halves atomic traffic; integer
//    accumulation is exactly order-independent.
//  - fused single-pass scan (decoupled lookback) that ALSO computes
//    dis = rsqrt(deg+1) from the same packed word and resets it.
//  - split-bf16 TC GEMMs, fp16 intermediates, CSR || GEMM1 fork as before.

#define HD   128
#define NMAX 100352
#define EMAX 1605632
#define WPAD 136          // padded k-stride (bf16 elems) for smem tiles

__device__ __align__(16) unsigned long long g_degcnt[NMAX]; // zero-init; reset by scan
__device__ __align__(16) float g_dis[NMAX];
__device__ __align__(16) int   g_row[EMAX];
__device__ __align__(16) int   g_col[EMAX];
__device__ __align__(16) int   g_batch[NMAX];
__device__ __align__(16) int   g_off[NMAX + 1];
__device__ __align__(16) int   g_cur[NMAX];
__device__ __align__(16) int   g_bsum[128];          // lookback aggregates+flag
__device__ __align__(16) int2  g_edge[EMAX];         // {src row, coef bits}
__device__ __align__(16) __half g_xwh[(size_t)NMAX * HD];  // GEMM1 out (fp16)
__device__ __align__(16) __half g_xwh2[(size_t)NMAX * HD]; // GEMM2 out (fp16)
__device__ __align__(16) __half g_hh[(size_t)NMAX * HD];   // agg out (fp16)
__device__ __align__(16) __nv_bfloat16 g_Wh[2][HD * HD];   // W^T hi, [n][k]
__device__ __align__(16) __nv_bfloat16 g_Wl[2][HD * HD];   // W^T lo

// ---------------------------------------------------------------------------
// dtype detection (int64 arrays have zero hi-words at odd 32-bit indices)
// ---------------------------------------------------------------------------
__device__ __forceinline__ int detect_ei64(const int* ei32)
{
    int lane = threadIdx.x & 31;
    int v = ei32[2 * lane + 1];
    return __all_sync(0xffffffffu, v == 0);
}

__device__ __forceinline__ int detect_b64(const int* b32, int n)
{
    int lane = threadIdx.x & 31;
    int base = (n > 64) ? ((n - 64) & ~1) : 0;
    int v = b32[base + 2 * lane + 1];
    return __all_sync(0xffffffffu, v == 0);
}

// ---------------------------------------------------------------------------
// prep1: convert edge_index + batch; ONE packed 64-bit atomic per edge
// (hi32 = count, lo32 = ew * 2^24 fixed point; cnt<=~64, sum<2^30 -> no carry)
// block 0 clears the lookback flags for the scan kernel.
// ---------------------------------------------------------------------------
__global__ void k_prep1(const void* __restrict__ ei, const void* __restrict__ bt,
                        const float* __restrict__ ew, int n, int e)
{
    __shared__ int s_ei64, s_b64;
    const int* ei32 = (const int*)ei;
    const int* bt32 = (const int*)bt;
    int tid = threadIdx.x;
    if (tid < 32) {
        int r = detect_ei64(ei32);
        if (tid == 0) s_ei64 = r;
    } else if (tid < 64) {
        int r = detect_b64(bt32, n);
        if (tid == 32) s_b64 = r;
    }
    if (blockIdx.x == 0 && tid < 128)
        g_bsum[tid] = 0;                 // clear lookback flags
    __syncthreads();

    int i = blockIdx.x * blockDim.x + tid;
    if (i < e) {
        int r, c;
        if (s_ei64) {
            const long long* p = (const long long*)ei;
            r = (int)p[i];
            c = (int)p[(size_t)e + i];
        } else {
            r = ei32[i];
            c = ei32[e + i];
        }
        g_row[i] = r;
        g_col[i] = c;
        unsigned fx = __float2uint_rn(ew[i] * 16777216.0f);   // ew * 2^24
        atomicAdd(&g_degcnt[c], (1ULL << 32) | (unsigned long long)fx);
    }
    if (i < n)
        g_batch[i] = s_b64 ? (int)((const long long*)bt)[i] : bt32[i];
}

// ---------------------------------------------------------------------------
// fused single-pass scan (decoupled lookback) + dis, one block type:
// read packed degcnt once -> cnt (scan) + deg (rsqrt); reset packed word.
// 98 blocks, all co-resident -> polling cannot deadlock.
// ---------------------------------------------------------------------------
__global__ void k_scan_all(int n, int e)
{
    __shared__ int s[1024];
    __shared__ int sbase;
    int b = blockIdx.x;
    int tid = threadIdx.x;
    int i = b * 1024 + tid;

    unsigned long long packed = 0;
    if (i < n) packed = g_degcnt[i];
    int v0 = (int)(packed >> 32);
    if (i < n) {
        float deg = (float)(unsigned)(packed & 0xffffffffu) * (1.0f / 16777216.0f);
        g_dis[i] = rsqrtf(deg + 1.0f);   // +1 = self-loop
        g_degcnt[i] = 0ULL;              // reset for next invocation
    }

    s[tid] = v0;
    __syncthreads();
    for (int off = 1; off < 1024; off <<= 1) {
        int t = 0;
        if (tid >= off) t = s[tid - off];
        __syncthreads();
        if (tid >= off) s[tid] += t;
        __syncthreads();
    }
    // publish this block's aggregate with flag (sign bit)
    if (tid == 0) {
        sbase = 0;
        atomicExch(&g_bsum[b], (int)(0x80000000u | (unsigned)s[1023]));
    }
    __syncthreads();
    // non-chained lookback: thread tid polls predecessor tid's aggregate
    if (tid < b) {
        unsigned v;
        do {
            v = (unsigned)atomicAdd(&g_bsum[tid], 0);
        } while (!(v & 0x80000000u));
        atomicAdd(&sbase, (int)(v & 0x7fffffffu));
    }
    __syncthreads();
    if (i < n) {
        int ex = sbase + s[tid] - v0;   // exclusive prefix
        g_off[i] = ex;
        g_cur[i] = ex;
    }
    if (b == 0 && tid == 0) g_off[n] = e;
}

__global__ void k_scatter(const float* __restrict__ ew, int e)
{
    int i = blockIdx.x * blockDim.x + threadIdx.x;
    if (i >= e) return;
    int r = g_row[i];
    int c = g_col[i];
    float coef = g_dis[r] * ew[i] * g_dis[c];
    int slot = atomicAdd(&g_cur[c], 1);
    g_edge[slot] = make_int2(r, __float_as_int(coef));
}

// ---------------------------------------------------------------------------
// W split: W[k][n] fp32 -> transposed bf16 hi/lo [n][k]
// ---------------------------------------------------------------------------
__global__ void k_wsplit(const float* __restrict__ W1, const float* __restrict__ W2)
{
    int idx = blockIdx.x * blockDim.x + threadIdx.x;
    if (idx >= HD * HD) return;
    int k = idx >> 7, nn = idx & 127;
    float w1 = W1[idx], w2 = W2[idx];
    __nv_bfloat16 h1 = __float2bfloat16(w1);
    __nv_bfloat16 h2 = __float2bfloat16(w2);
    int o = nn * HD + k;
    g_Wh[0][o] = h1;
    g_Wl[0][o] = __float2bfloat16(w1 - __bfloat162float(h1));
    g_Wh[1][o] = h2;
    g_Wl[1][o] = __float2bfloat16(w2 - __bfloat162float(h2));
}

// ---------------------------------------------------------------------------
// tensor-core GEMM: Cout[rows x 128] = A[rows x 128] @ W  (split-bf16)
// A = Xin (fp32) when useH=0, g_hh (fp16) when useH=1.
// Cout: g_xwh (useH=0) or g_xwh2 (useH=1).
// ---------------------------------------------------------------------------
#define MMA16816(d, a, b)                                                     \
    asm volatile("mma.sync.aligned.m16n8k16.row.col.f32.bf16.bf16.f32 "       \
                 "{%0,%1,%2,%3}, {%4,%5,%6,%7}, {%8,%9}, {%0,%1,%2,%3};"      \
                 : "+f"((d)[0]), "+f"((d)[1]), "+f"((d)[2]), "+f"((d)[3])     \
                 : "r"((a)[0]), "r"((a)[1]), "r"((a)[2]), "r"((a)[3]),        \
                   "r"((b)[0]), "r"((b)[1]))

__global__ void __launch_bounds__(256) k_gemm_tc(const float* __restrict__ Xin,
                                                 int widx, int useH, int n)
{
    extern __shared__ __align__(16) char smraw[];
    __nv_bfloat16* Ah = (__nv_bfloat16*)smraw;       // [128][WPAD]
    __nv_bfloat16* Al = Ah + 128 * WPAD;
    __nv_bfloat16* Bh = Al + 128 * WPAD;             // W^T [n][k], [128][WPAD]
    __nv_bfloat16* Bl = Bh + 128 * WPAD;

    __half* Cout = useH ? g_xwh2 : g_xwh;
    int tid = threadIdx.x;
    int rowBase = blockIdx.x * 128;

    // stage + split A tile
#pragma unroll
    for (int i = 0; i < 16; i++) {
        int f4 = tid + i * 256;
        int r = f4 >> 5;
        int c4 = (f4 & 31) * 4;
        int ar = min(rowBase + r, n - 1);
        float4 v;
        if (useH) {
            uint2 hv = *(const uint2*)(g_hh + (size_t)ar * HD + c4);
            float2 f01 = __half22float2(*(__half2*)&hv.x);
            float2 f23 = __half22float2(*(__half2*)&hv.y);
            v = make_float4(f01.x, f01.y, f23.x, f23.y);
        } else {
            v = *(const float4*)(Xin + (size_t)ar * HD + c4);
        }
        __nv_bfloat16 hx = __float2bfloat16(v.x);
        __nv_bfloat16 hy = __float2bfloat16(v.y);
        __nv_bfloat16 hz = __float2bfloat16(v.z);
        __nv_bfloat16 hw = __float2bfloat16(v.w);
        __nv_bfloat16 lx = __float2bfloat16(v.x - __bfloat162float(hx));
        __nv_bfloat16 ly = __float2bfloat16(v.y - __bfloat162float(hy));
        __nv_bfloat16 lz = __float2bfloat16(v.z - __bfloat162float(hz));
        __nv_bfloat16 lw = __float2bfloat16(v.w - __bfloat162float(hw));
        __nv_bfloat162 h01, h23, l01, l23;
        h01.x = hx; h01.y = hy; h23.x = hz; h23.y = hw;
        l01.x = lx; l01.y = ly; l23.x = lz; l23.y = lw;
        uint2 uh, ul;
        uh.x = *(uint32_t*)&h01; uh.y = *(uint32_t*)&h23;
        ul.x = *(uint32_t*)&l01; ul.y = *(uint32_t*)&l23;
        *(uint2*)&Ah[r * WPAD + c4] = uh;
        *(uint2*)&Al[r * WPAD + c4] = ul;
    }

    // stage W^T tiles
#pragma unroll
    for (int i = 0; i < 8; i++) {
        int idx8 = (tid + i * 256) * 8;
        int r = idx8 >> 7;
        int c = idx8 & 127;
        *(uint4*)&Bh[r * WPAD + c] = *(const uint4*)&g_Wh[widx][idx8];
        *(uint4*)&Bl[r * WPAD + c] = *(const uint4*)&g_Wl[widx][idx8];
    }
    __syncthreads();

    int lane = tid & 31;
    int w = tid >> 5;
    int g = lane >> 2;
    int t = lane & 3;
    int wm0 = (w & 1) * 64;
    int wn0 = (w >> 1) * 32;

    float acc[4][4][4];
#pragma unroll
    for (int mb = 0; mb < 4; mb++)
#pragma unroll
        for (int nb = 0; nb < 4; nb++)
#pragma unroll
            for (int q = 0; q < 4; q++) acc[mb][nb][q] = 0.0f;

#pragma unroll
    for (int ks = 0; ks < 8; ks++) {
        int k0 = ks * 16 + t * 2;
        uint32_t ah[4][4], al[4][4];
#pragma unroll
        for (int mb = 0; mb < 4; mb++) {
            int r0 = wm0 + mb * 16 + g;
            ah[mb][0] = *(const uint32_t*)&Ah[r0 * WPAD + k0];
            ah[mb][1] = *(const uint32_t*)&Ah[(r0 + 8) * WPAD + k0];
            ah[mb][2] = *(const uint32_t*)&Ah[r0 * WPAD + k0 + 8];
            ah[mb][3] = *(const uint32_t*)&Ah[(r0 + 8) * WPAD + k0 + 8];
            al[mb][0] = *(const uint32_t*)&Al[r0 * WPAD + k0];
            al[mb][1] = *(const uint32_t*)&Al[(r0 + 8) * WPAD + k0];
            al[mb][2] = *(const uint32_t*)&Al[r0 * WPAD + k0 + 8];
            al[mb][3] = *(const uint32_t*)&Al[(r0 + 8) * WPAD + k0 + 8];
        }
        uint32_t bh[4][2], bl[4][2];
#pragma unroll
        for (int nb = 0; nb < 4; nb++) {
            int nr = wn0 + nb * 8 + g;
            bh[nb][0] = *(const uint32_t*)&Bh[nr * WPAD + k0];
            bh[nb][1] = *(const uint32_t*)&Bh[nr * WPAD + k0 + 8];
            bl[nb][0] = *(const uint32_t*)&Bl[nr * WPAD + k0];
            bl[nb][1] = *(const uint32_t*)&Bl[nr * WPAD + k0 + 8];
        }
#pragma unroll
        for (int mb = 0; mb < 4; mb++)
#pragma unroll
            for (int nb = 0; nb < 4; nb++) {
                MMA16816(acc[mb][nb], ah[mb], bh[nb]);
                MMA16816(acc[mb][nb], ah[mb], bl[nb]);
                MMA16816(acc[mb][nb], al[mb], bh[nb]);
            }
    }

    // write C as fp16
#pragma unroll
    for (int mb = 0; mb < 4; mb++) {
#pragma unroll
        for (int nb = 0; nb < 4; nb++) {
            int r0 = rowBase + wm0 + mb * 16 + g;
            int c0 = wn0 + nb * 8 + t * 2;
            if (r0 < n) {
                __half2 v0 = __floats2half2_rn(acc[mb][nb][0], acc[mb][nb][1]);
                *(__half2*)&Cout[(size_t)r0 * HD + c0] = v0;
            }
            if (r0 + 8 < n) {
                __half2 v1 = __floats2half2_rn(acc[mb][nb][2], acc[mb][nb][3]);
                *(__half2*)&Cout[(size_t)(r0 + 8) * HD + c0] = v1;
            }
        }
    }
}

// ---------------------------------------------------------------------------
// aggregation: fp16 gathers, fp32 accumulate, fp16 output to g_hh.
// warp per node, full grid. srcSel: 0 -> g_xwh, 1 -> g_xwh2.
// ---------------------------------------------------------------------------
__device__ __forceinline__ void h4_acc(float4& acc, uint2 u, float c)
{
    float2 f01 = __half22float2(*(__half2*)&u.x);
    float2 f23 = __half22float2(*(__half2*)&u.y);
    acc.x += c * f01.x;
    acc.y += c * f01.y;
    acc.z += c * f23.x;
    acc.w += c * f23.y;
}

__global__ void k_agg(const float* __restrict__ bias, int srcSel, int n)
{
    int gw = (blockIdx.x * blockDim.x + threadIdx.x) >> 5;
    int lane = threadIdx.x & 31;
    if (gw >= n) return;

    const uint2* x2 = (const uint2*)(srcSel ? g_xwh2 : g_xwh);
    float sc = g_dis[gw];
    float4 acc = make_float4(0.f, 0.f, 0.f, 0.f);
    h4_acc(acc, x2[(size_t)gw * 32 + lane], sc * sc);

    int p  = g_off[gw];
    int p1 = g_off[gw + 1];
    for (; p + 3 < p1; p += 4) {
        int2 e0 = g_edge[p];
        int2 e1 = g_edge[p + 1];
        int2 e2 = g_edge[p + 2];
        int2 e3 = g_edge[p + 3];
        uint2 u0 = x2[(size_t)e0.x * 32 + lane];
        uint2 u1 = x2[(size_t)e1.x * 32 + lane];
        uint2 u2 = x2[(size_t)e2.x * 32 + lane];
        uint2 u3 = x2[(size_t)e3.x * 32 + lane];
        h4_acc(acc, u0, __int_as_float(e0.y));
        h4_acc(acc, u1, __int_as_float(e1.y));
        h4_acc(acc, u2, __int_as_float(e2.y));
        h4_acc(acc, u3, __int_as_float(e3.y));
    }
    for (; p < p1; p++) {
        int2 e0 = g_edge[p];
        uint2 u0 = x2[(size_t)e0.x * 32 + lane];
        h4_acc(acc, u0, __int_as_float(e0.y));
    }

    float4 bb = ((const float4*)bias)[lane];
    __half2 h01 = __floats2half2_rn(fmaxf(acc.x + bb.x, 0.0f),
                                    fmaxf(acc.y + bb.y, 0.0f));
    __half2 h23 = __floats2half2_rn(fmaxf(acc.z + bb.z, 0.0f),
                                    fmaxf(acc.w + bb.w, 0.0f));
    uint2 u;
    u.x = *(uint32_t*)&h01;
    u.y = *(uint32_t*)&h23;
    *(uint2*)&g_hh[(size_t)gw * HD + 4 * lane] = u;
}

// ---------------------------------------------------------------------------
// pooling + classifier over fp16 g_hh (binary-search graph bounds)
// ---------------------------------------------------------------------------
__global__ void k_poolfinal(const float* __restrict__ Wl, const float* __restrict__ bl,
                            float* __restrict__ out, int n)
{
    int g = blockIdx.x;
    int f = threadIdx.x;
    __shared__ int sb[2];
    __shared__ float r0[128], r1[128];

    if (f < 2) {
        int target = g + f;
        int lo = 0, hi = n;
        while (lo < hi) {
            int mid = (lo + hi) >> 1;
            if (g_batch[mid] < target) lo = mid + 1; else hi = mid;
        }
        sb[f] = lo;
    }
    __syncthreads();
    int s = sb[0], t = sb[1];

    float acc = 0.0f;
    for (int i = s; i < t; i++)
        acc += __half2float(g_hh[(size_t)i * HD + f]);
    float pooled = acc / fmaxf((float)(t - s), 1.0f);

    r0[f] = pooled * Wl[f * 2 + 0];
    r1[f] = pooled * Wl[f * 2 + 1];
    __syncthreads();
#pragma unroll
    for (int off = 64; off > 0; off >>= 1) {
        if (f < off) { r0[f] += r0[f + off]; r1[f] += r1[f + off]; }
        __syncthreads();
    }
    if (f == 0) {
        out[g * 2 + 0] = r0[0] + bl[0];
        out[g * 2 + 1] = r1[0] + bl[1];
    }
}

// ---------------------------------------------------------------------------
static inline int ceil_div_i(int a, int b) { return (a + b - 1) / b; }

extern "C" void kernel_launch(void* const* d_in, const int* in_sizes, int n_in,
                              void* d_out, int out_size)
{
    (void)n_in;
    const float* x  = (const float*)d_in[0];
    const void*  ei = d_in[1];
    const float* ew = (const float*)d_in[2];
    const void*  bt = d_in[3];
    const float* W1 = (const float*)d_in[4];
    const float* b1 = (const float*)d_in[5];
    const float* W2 = (const float*)d_in[6];
    const float* b2 = (const float*)d_in[7];
    const float* Wl = (const float*)d_in[8];
    const float* bl = (const float*)d_in[9];
    float* out = (float*)d_out;

    int n = in_sizes[0] / HD;
    int e = in_sizes[2];
    int G = out_size / 2;

    int eb = ceil_div_i(e, 256);
    int nb = ceil_div_i(n, 1024);
    int gemm_blocks = ceil_div_i(n, 128);
    int agg_blocks  = ceil_div_i(n, 8);

    int gemm_smem = 4 * 128 * WPAD * (int)sizeof(__nv_bfloat16);  // 139264
    cudaFuncSetAttribute(k_gemm_tc, cudaFuncAttributeMaxDynamicSharedMemorySize,
                         gemm_smem);

    // fork side stream: wsplit + GEMM1 overlap the CSR build chain
    cudaStream_t s2 = 0;
    cudaEvent_t evA = 0, evB = 0;
    bool forked = false;
    if (cudaStreamCreateWithFlags(&s2, cudaStreamNonBlocking) == cudaSuccess &&
        cudaEventCreateWithFlags(&evA, cudaEventDisableTiming) == cudaSuccess &&
        cudaEventCreateWithFlags(&evB, cudaEventDisableTiming) == cudaSuccess) {
        if (cudaEventRecord(evA, 0) == cudaSuccess &&
            cudaStreamWaitEvent(s2, evA, 0) == cudaSuccess)
            forked = true;
    }

    cudaStream_t gs = forked ? s2 : (cudaStream_t)0;
    k_wsplit<<<ceil_div_i(HD * HD, 256), 256, 0, gs>>>(W1, W2);
    k_gemm_tc<<<gemm_blocks, 256, gemm_smem, gs>>>(x, 0, 0, n);
    if (forked) cudaEventRecord(evB, gs);

    // CSR build chain on main stream (g_degcnt pre-zeroed; prep1 clears flags)
    k_prep1<<<eb, 256>>>(ei, bt, ew, n, e);
    k_scan_all<<<nb, 1024>>>(n, e);
    k_scatter<<<eb, 256>>>(ew, e);

    if (forked) cudaStreamWaitEvent(0, evB, 0);

    // layer 1 aggregate -> layer 2 GEMM -> layer 2 aggregate (full grids)
    k_agg<<<agg_blocks, 256>>>(b1, 0, n);                     // g_xwh  -> g_hh
    k_gemm_tc<<<gemm_blocks, 256, gemm_smem>>>(x, 1, 1, n);   // g_hh  -> g_xwh2
    k_agg<<<agg_blocks, 256>>>(b2, 1, n);                     // g_xwh2 -> g_hh

    // pooling + classifier
    k_poolfinal<<<G, 128>>>(Wl, bl, out, n);
}